// round 15
// baseline (speedup 1.0000x reference)
#include <cuda_runtime.h>
#include <math.h>

#define NB 32
static constexpr int TPB   = 128;
static constexpr int PSLOT = 36;                      // padded bins (-2..33) one term
static constexpr int SMEM_BYTES = PSLOT * TPB * 8;    // 36864
static constexpr int BUFSZ = 1 << 22;                 // candidate buffer entries per array

// ---------------- radix-select global state ----------------
__device__ int g_hist4[4][2][4][256];                 // per-pass histogram buffers
__device__ unsigned g_bufA[BUFSZ];
__device__ unsigned g_bufB[BUFSZ];

struct TermP {
    float flo, fhi, mlo, mhi, t0, is, QhSW, Q9SW, SXoSW;
    float ac[7], cc[5], sc[5];
    double SXinv, SSX, SSXX, SSXinv, SSXXinv;
};

// exact global accumulators (integer atomics -> deterministic)
__device__ unsigned long long g_accH[64];
__device__ unsigned long long g_accL[64];
__device__ unsigned long long g_accS[4];

// ---------------- grid barrier (sense reversing) ----------------
__device__ unsigned g_arrive = 0;
__device__ unsigned g_gen = 0;

__device__ __forceinline__ void gridbar() {
    __threadfence();
    __syncthreads();
    if (threadIdx.x == 0) {
        unsigned gen = *(volatile unsigned*)&g_gen;
        unsigned prev = atomicAdd(&g_arrive, 1u);
        if (prev == gridDim.x - 1u) {
            g_arrive = 0u;
            __threadfence();
            *(volatile unsigned*)&g_gen = gen + 1u;
        } else {
            while (*(volatile unsigned*)&g_gen == gen) __nanosleep(64);
        }
        __threadfence();
    }
    __syncthreads();
}

__device__ __forceinline__ unsigned f2key(float f) {
    unsigned u = __float_as_uint(f);
    return (u & 0x80000000u) ? ~u : (u | 0x80000000u);
}
__device__ __forceinline__ float key2f(unsigned k) {
    unsigned u = (k & 0x80000000u) ? (k & 0x7FFFFFFFu) : ~k;
    return __uint_as_float(u);
}

// ws is already weight*SW; xr = x*SX/SW so lw = w*x*SX
__device__ __forceinline__ unsigned long long pack2s(float ws, float xr) {
    unsigned hw = __float2uint_rn(ws);
    int lw = __float2int_rn(ws * xr);
    return ((unsigned long long)hw << 32) + (unsigned long long)(long long)lw;
}

// ---------------- one-term Parzen pass (4-bin window, prefetch, trimmed polys) ----
__device__ __forceinline__ void parzen_pass(
    const float4* __restrict__ Y4, const float4* __restrict__ X4,
    const float* __restrict__ Ys, const float* __restrict__ Xs,
    const TermP* tg, int term, int N, int N4, int gid, int gsz,
    unsigned long long* priv)
{
    __shared__ float s_red[2][TPB / 32];
    int t = threadIdx.x;
    float flo = tg->flo, fhi = tg->fhi, mlo = tg->mlo, mhi = tg->mhi;
    float t0 = tg->t0, is = tg->is;
    float QhSW = tg->QhSW, Q9SW = tg->Q9SW, SXoSW = tg->SXoSW;
    float ac[7], cc[5], sc[5];
    #pragma unroll
    for (int k = 0; k < 7; k++) ac[k] = tg->ac[k];
    #pragma unroll
    for (int k = 0; k < 5; k++) { cc[k] = tg->cc[k]; sc[k] = tg->sc[k]; }

    #pragma unroll
    for (int s = 0; s < PSLOT; s++) priv[s * TPB + t] = 0ull;
    __syncthreads();

    unsigned long long* col = priv + t;
    float sx = 0.f, sxx = 0.f;

    // software-pipelined main loop: prefetch next iteration's float4 pair
    int i = gid;
    bool valid = (i < N4);
    float4 y4, x4;
    if (valid) { y4 = Y4[i]; x4 = X4[i]; }
    while (valid) {
        int inext = i + gsz;
        bool vnext = (inext < N4);
        float4 yn = y4, xn = x4;
        if (vnext) { yn = Y4[inext]; xn = X4[inext]; }

        float ye[4] = {y4.x, y4.y, y4.z, y4.w};
        float xe[4] = {x4.x, x4.y, x4.z, x4.w};
        #pragma unroll
        for (int e = 0; e < 4; e++) {
            float y = fminf(fmaxf(ye[e], flo), fhi);
            float x = fminf(fmaxf(xe[e], mlo), mhi);
            sx += x; sxx = fmaf(x, x, sxx);
            float g = (y - t0) * is;              // in [-0.5, 31.5]
            float rf = floorf(g);
            int r = (int)rf;
            r = min(max(r, -1), NB - 1);          // hard in-bounds
            float v = (g - rf) - 0.5f;            // in [-0.5, 0.5]
            float s = v * v;
            float Av = ac[6];
            #pragma unroll
            for (int k = 5; k >= 0; k--) Av = fmaf(Av, s, ac[k]);   // e^{-c v^2}
            float C = cc[4];
            #pragma unroll
            for (int k = 3; k >= 0; k--) C = fmaf(C, s, cc[k]);     // cosh(c v)
            float Sp = sc[4];
            #pragma unroll
            for (int k = 3; k >= 0; k--) Sp = fmaf(Sp, s, sc[k]);   // sinh(c v)/v
            float S = Sp * v;
            float G = C + S, Gi = C - S;          // e^{+cv}, e^{-cv}
            float a1s = Av * QhSW, a9s = Av * Q9SW;   // SW folded in
            float xr = x * SXoSW;
            float Gi2 = Gi * Gi, G2 = G * G;
            unsigned long long* p = col + (unsigned)(r + 1) * (unsigned)TPB;
            p[0]       = p[0]       + pack2s(a9s * (Gi * Gi2), xr);  // bin r-1
            p[TPB]     = p[TPB]     + pack2s(a1s * Gi, xr);          // bin r
            p[2 * TPB] = p[2 * TPB] + pack2s(a1s * G, xr);           // bin r+1
            p[3 * TPB] = p[3 * TPB] + pack2s(a9s * (G * G2), xr);    // bin r+2
        }
        y4 = yn; x4 = xn; i = inext; valid = vnext;
    }
    if (gid == 0) {
        for (int rr = N4 << 2; rr < N; rr++) {
            float y = fminf(fmaxf(Ys[rr], flo), fhi);
            float x = fminf(fmaxf(Xs[rr], mlo), mhi);
            sx += x; sxx = fmaf(x, x, sxx);
            float g = (y - t0) * is;
            float rf = floorf(g);
            int r = (int)rf;
            r = min(max(r, -1), NB - 1);
            float v = (g - rf) - 0.5f;
            float s = v * v;
            float Av = ac[6];
            for (int k = 5; k >= 0; k--) Av = fmaf(Av, s, ac[k]);
            float C = cc[4];
            for (int k = 3; k >= 0; k--) C = fmaf(C, s, cc[k]);
            float Sp = sc[4];
            for (int k = 3; k >= 0; k--) Sp = fmaf(Sp, s, sc[k]);
            float S = Sp * v;
            float G = C + S, Gi = C - S;
            float a1s = Av * QhSW, a9s = Av * Q9SW;
            float xr = x * SXoSW;
            unsigned long long* p = col + (unsigned)(r + 1) * (unsigned)TPB;
            p[0]       = p[0]       + pack2s(a9s * (Gi * Gi * Gi), xr);
            p[TPB]     = p[TPB]     + pack2s(a1s * Gi, xr);
            p[2 * TPB] = p[2 * TPB] + pack2s(a1s * G, xr);
            p[3 * TPB] = p[3 * TPB] + pack2s(a9s * (G * G * G), xr);
        }
    }

    int lane = t & 31, warp = t >> 5;
    #pragma unroll
    for (int off = 16; off; off >>= 1) {
        sx  += __shfl_down_sync(0xFFFFFFFFu, sx,  off);
        sxx += __shfl_down_sync(0xFFFFFFFFu, sxx, off);
    }
    if (lane == 0) { s_red[0][warp] = sx; s_red[1][warp] = sxx; }
    __syncthreads();   // orders priv writes + s_red

    if (t < NB) {
        unsigned long long H = 0; long long L = 0;
        #pragma unroll 4
        for (int jj = 0; jj < TPB; jj++) {
            int j = (jj + t) & (TPB - 1);
            unsigned long long v = priv[(t + 2) * TPB + j];
            int lo = (int)(unsigned)v;
            unsigned hi = (unsigned)(v >> 32) + ((lo < 0) ? 1u : 0u);
            H += hi; L += lo;
        }
        atomicAdd(&g_accH[term * NB + t], H);
        atomicAdd(&g_accL[term * NB + t], (unsigned long long)L);
    }
    if (t == 0) {
        double bsx = 0.0, bsxx = 0.0;
        #pragma unroll
        for (int w = 0; w < TPB / 32; w++) { bsx += (double)s_red[0][w]; bsxx += (double)s_red[1][w]; }
        long long v1 = __double2ll_rn(bsx * tg->SSX);
        long long v2 = __double2ll_rn(bsxx * tg->SSXX);
        atomicAdd(&g_accS[term * 2 + 0], (unsigned long long)v1);
        atomicAdd(&g_accS[term * 2 + 1], (unsigned long long)v2);
    }
    __syncthreads();
}

__global__ void __launch_bounds__(TPB, 6)
k_fused(const float* __restrict__ A, const float* __restrict__ B, int N,
        unsigned k01, unsigned k99, float f01, float f99, int epb, int reg,
        float* __restrict__ out)
{
    extern __shared__ unsigned long long dyn[];
    unsigned long long* priv = dyn;
    int* shist = (int*)dyn;
    __shared__ int s_cntA, s_cntB;
    __shared__ unsigned s_pref[2][4], s_rank[2][4], s_key[2][4];
    __shared__ TermP s_tp[2];
    __shared__ double s_SWinv;

    int t = threadIdx.x;
    int nb = gridDim.x;
    int gsz = nb * TPB;
    int gid = blockIdx.x * TPB + t;
    const float4* A4 = (const float4*)A;
    const float4* B4 = (const float4*)B;
    int N4 = N >> 2;

    // per-block radix state; grid-wide zeroing of global buffers
    if (t < 8) {
        int a = t >> 2, j = t & 3;
        s_pref[a][j] = 0u;
        s_rank[a][j] = (j < 2 ? k01 : k99) + (unsigned)(j & 1);
    }
    for (int i = gid; i < 8192; i += gsz) ((int*)g_hist4)[i] = 0;
    if (gid < 64) { g_accH[gid] = 0ull; g_accL[gid] = 0ull; }
    if (gid < 4) g_accS[gid] = 0ull;
    gridbar();   // barrier 1

    // ============ quantile: 4 radix passes, ONE gridbar per pass ============
    for (int pass = 0; pass < 4; pass++) {
        for (int i = t; i < 2048; i += TPB) shist[i] = 0;
        if (pass == 1 && t == 0) { s_cntA = 0; s_cntB = 0; }
        __syncthreads();
        if (pass == 0) {
            int ca = (t & 3) * 256, cb = (4 + (t & 3)) * 256;
            for (int i = gid; i < N4; i += gsz) {
                float4 va = A4[i], vb = B4[i];
                atomicAdd(&shist[ca + (f2key(va.x) >> 24)], 1);
                atomicAdd(&shist[ca + (f2key(va.y) >> 24)], 1);
                atomicAdd(&shist[ca + (f2key(va.z) >> 24)], 1);
                atomicAdd(&shist[ca + (f2key(va.w) >> 24)], 1);
                atomicAdd(&shist[cb + (f2key(vb.x) >> 24)], 1);
                atomicAdd(&shist[cb + (f2key(vb.y) >> 24)], 1);
                atomicAdd(&shist[cb + (f2key(vb.z) >> 24)], 1);
                atomicAdd(&shist[cb + (f2key(vb.w) >> 24)], 1);
            }
            if (gid == 0) {
                for (int r = N4 << 2; r < N; r++) {
                    atomicAdd(&shist[0 * 256 + (f2key(A[r]) >> 24)], 1);
                    atomicAdd(&shist[4 * 256 + (f2key(B[r]) >> 24)], 1);
                }
            }
        } else if (pass == 1) {
            unsigned pa[4], pb[4];
            #pragma unroll
            for (int j = 0; j < 4; j++) { pa[j] = s_pref[0][j]; pb[j] = s_pref[1][j]; }
            unsigned baseA = (unsigned)blockIdx.x * (unsigned)reg;
            for (int i = gid; i < N4; i += gsz) {
                float4 va = A4[i], vb = B4[i];
                float ea[4] = {va.x, va.y, va.z, va.w};
                float eb[4] = {vb.x, vb.y, vb.z, vb.w};
                #pragma unroll
                for (int e = 0; e < 4; e++) {
                    unsigned k = f2key(ea[e]);
                    unsigned top = k >> 24, b = (k >> 16) & 255u;
                    bool m = false;
                    #pragma unroll
                    for (int j = 0; j < 4; j++)
                        if (top == pa[j]) { atomicAdd(&shist[j * 256 + b], 1); m = true; }
                    if (m) {
                        int pos = atomicAdd(&s_cntA, 1);
                        if (pos < reg) g_bufA[baseA + pos] = k;
                    }
                    k = f2key(eb[e]);
                    top = k >> 24; b = (k >> 16) & 255u;
                    m = false;
                    #pragma unroll
                    for (int j = 0; j < 4; j++)
                        if (top == pb[j]) { atomicAdd(&shist[(4 + j) * 256 + b], 1); m = true; }
                    if (m) {
                        int pos = atomicAdd(&s_cntB, 1);
                        if (pos < reg) g_bufB[baseA + pos] = k;
                    }
                }
            }
            if (gid == 0) {
                for (int r = N4 << 2; r < N; r++) {
                    unsigned k = f2key(A[r]);
                    unsigned top = k >> 24, b = (k >> 16) & 255u;
                    bool m = false;
                    for (int j = 0; j < 4; j++)
                        if (top == pa[j]) { atomicAdd(&shist[j * 256 + b], 1); m = true; }
                    if (m) {
                        int pos = atomicAdd(&s_cntA, 1);
                        if (pos < reg) g_bufA[baseA + pos] = k;
                    }
                    k = f2key(B[r]); top = k >> 24; b = (k >> 16) & 255u;
                    m = false;
                    for (int j = 0; j < 4; j++)
                        if (top == pb[j]) { atomicAdd(&shist[(4 + j) * 256 + b], 1); m = true; }
                    if (m) {
                        int pos = atomicAdd(&s_cntB, 1);
                        if (pos < reg) g_bufB[baseA + pos] = k;
                    }
                }
            }
        } else {
            unsigned pa[4], pb[4];
            #pragma unroll
            for (int j = 0; j < 4; j++) { pa[j] = s_pref[0][j]; pb[j] = s_pref[1][j]; }
            int ms = 32 - 8 * pass, bs = 24 - 8 * pass;
            unsigned baseA = (unsigned)blockIdx.x * (unsigned)reg;
            int cntA = min(s_cntA, reg), cntB = min(s_cntB, reg);
            for (int i = t; i < cntA; i += TPB) {
                unsigned k = g_bufA[baseA + i];
                unsigned top = k >> ms, b = (k >> bs) & 255u;
                #pragma unroll
                for (int j = 0; j < 4; j++)
                    if (top == pa[j]) atomicAdd(&shist[j * 256 + b], 1);
            }
            for (int i = t; i < cntB; i += TPB) {
                unsigned k = g_bufB[baseA + i];
                unsigned top = k >> ms, b = (k >> bs) & 255u;
                #pragma unroll
                for (int j = 0; j < 4; j++)
                    if (top == pb[j]) atomicAdd(&shist[(4 + j) * 256 + b], 1);
            }
        }
        __syncthreads();
        for (int i = t; i < 2048; i += TPB) {
            int v = shist[i];
            if (v) {
                int row = i >> 8, bin = i & 255;
                int a = row >> 2;
                int j = (pass == 0) ? 0 : (row & 3);
                atomicAdd(&g_hist4[pass][a][j][bin], v);
            }
        }
        gridbar();   // one barrier per pass (2..5)

        // redundant scan in EVERY block (deterministic, removes 2nd barrier)
        {
            int warp = t >> 5, lane = t & 31;
            for (int q = warp; q < 8; q += 4) {
                int a = q >> 2, jj = q & 3;
                int jsel = (pass == 0) ? 0 : jj;
                const int* h = &g_hist4[pass][a][jsel][0];
                int c[8]; int ps = 0;
                #pragma unroll
                for (int k = 0; k < 8; k++) { c[k] = __ldcg(h + lane * 8 + k); ps += c[k]; }
                int v = ps;
                #pragma unroll
                for (int off = 1; off < 32; off <<= 1) {
                    int n = __shfl_up_sync(0xFFFFFFFFu, v, off);
                    if (lane >= off) v += n;
                }
                unsigned excl = (unsigned)(v - ps);
                unsigned rank = s_rank[a][jj];
                bool has = (rank >= excl) && (rank < excl + (unsigned)ps);
                if (has) {
                    unsigned cum = excl; int d = 0;
                    #pragma unroll
                    for (int k = 0; k < 8; k++) {
                        if (cum + (unsigned)c[k] > rank) { d = k; break; }
                        cum += (unsigned)c[k];
                    }
                    unsigned np = (s_pref[a][jj] << 8) | (unsigned)(lane * 8 + d);
                    s_pref[a][jj] = np;
                    s_rank[a][jj] = rank - cum;
                    if (pass == 3) s_key[a][jj] = np;
                }
            }
            __syncthreads();
        }
    }

    // ============ per-block params (redundant, deterministic) ============
    if (t == 0) {
        float q[2][2];
        for (int a = 0; a < 2; a++) {
            float v0 = key2f(s_key[a][0]), v1 = key2f(s_key[a][1]);
            q[a][0] = v0 + f01 * (v1 - v0);
            v0 = key2f(s_key[a][2]); v1 = key2f(s_key[a][3]);
            q[a][1] = v0 + f99 * (v1 - v0);
        }
        const float sigma_ratio = (float)(1.0 / 2.355);
        float swf = exp2f(floorf(log2f(1073741824.0f / (float)epb)));
        s_SWinv = 1.0 / (double)swf;
        for (int term = 0; term < 2; term++) {
            TermP& tp = s_tp[term];
            int pa2 = term, ta2 = 1 - term;
            float flo = q[ta2][0], fhi = q[ta2][1];
            tp.flo = flo; tp.fhi = fhi;
            tp.mlo = q[pa2][0]; tp.mhi = q[pa2][1];
            float fb = (fhi - flo) / (float)NB;
            float lo = flo + 0.5f * fb, hi = fhi - 0.5f * fb;
            float step = (hi - lo) / (float)(NB - 1);
            float sd = 0.f, prev = lo;
            for (int i = 1; i < NB; i++) { float v = lo + step * (float)i; sd += v - prev; prev = v; }
            float fs = (sd / (float)(NB - 1)) * sigma_ratio;
            float preterm = 1.0f / (2.0f * fs * fs);
            tp.t0 = lo; tp.is = 1.0f / step;
            double c = (double)preterm * (double)step * (double)step;
            double a = 1.0; tp.ac[0] = 1.0f;
            for (int k = 1; k <= 6; k++) { a *= (-c) / (double)k; tp.ac[k] = (float)a; }
            double X = c * c;
            double tm = 1.0; tp.cc[0] = 1.0f;
            for (int m = 1; m <= 4; m++) { tm *= X / ((double)(2 * m - 1) * (double)(2 * m)); tp.cc[m] = (float)tm; }
            double st = c; tp.sc[0] = (float)c;
            for (int m = 1; m <= 4; m++) { st *= X / ((double)(2 * m) * (double)(2 * m + 1)); tp.sc[m] = (float)st; }
            double Qh = exp(-0.25 * c), Qh9 = exp(-2.25 * c);
            tp.QhSW = (float)(Qh * (double)swf);
            tp.Q9SW = (float)(Qh9 * (double)swf);
            float xm = fmaxf(fabsf(tp.mlo), fabsf(tp.mhi));
            if (xm < 1e-20f) xm = 1e-20f;
            float sxs = exp2f(floorf(log2f(1073741824.0f / ((float)epb * xm))));
            tp.SXoSW = sxs / swf;            // exact (both powers of 2)
            tp.SXinv = 1.0 / (double)sxs;
            double nx = (double)N * (double)xm;
            tp.SSX = exp2(floor(log2(2.3e18 / nx)));
            tp.SSXinv = 1.0 / tp.SSX;
            double nxx = nx * (double)xm;
            tp.SSXX = exp2(floor(log2(2.3e18 / nxx)));
            tp.SSXXinv = 1.0 / tp.SSXX;
        }
    }
    __syncthreads();

    // ====== Parzen phase: ONE pass, terms split across blocks by parity ======
    {
        int term = blockIdx.x & 1;
        int gid2 = (blockIdx.x >> 1) * TPB + t;
        int gsz2 = (nb >> 1) * TPB;
        if (term == 0)
            parzen_pass(B4, A4, B, A, &s_tp[0], 0, N, N4, gid2, gsz2, priv);
        else
            parzen_pass(A4, B4, A, B, &s_tp[1], 1, N, N4, gid2, gsz2, priv);
    }
    gridbar();   // barrier 6

    // ================= final (block 0) =================
    if (blockIdx.x == 0) {
        unsigned long long* stage = dyn;   // [0..63]=H, [64..127]=L, [128..131]=S
        if (t < 64) { stage[t] = __ldcg(&g_accH[t]); stage[64 + t] = __ldcg(&g_accL[t]); }
        if (t >= 64 && t < 68) stage[128 + (t - 64)] = __ldcg(&g_accS[t - 64]);
        __syncthreads();
        if (t == 0) {
            const double eps = 1.1920928955078125e-07;
            double dN = (double)N;
            double swi = s_SWinv;
            double eta = 0.0;
            for (int term = 0; term < 2; term++) {
                double sxi = s_tp[term].SXinv;
                double sx  = (double)(long long)stage[128 + 2 * term]     * s_tp[term].SSXinv;
                double sxx = (double)(long long)stage[128 + 2 * term + 1] * s_tp[term].SSXXinv;
                double mean = sx / dN;
                double Ssw = 0.0, num = 0.0;
                for (int j = 0; j < NB; j++) {
                    double sw  = (double)stage[term * NB + j] * swi;
                    double swx = (double)(long long)stage[64 + term * NB + j] * sxi;
                    double m = swx / (sw + eps);
                    double d = m - mean;
                    num += sw * d * d;
                    Ssw += sw;
                }
                double bgv = num / (Ssw + eps);
                double var = (sxx - sx * sx / dN) / (dN - 1.0);
                eta += bgv / (var + eps);
            }
            out[0] = (float)(-0.5 * eta);
        }
    }
}

extern "C" void kernel_launch(void* const* d_in, const int* in_sizes, int n_in,
                              void* d_out, int out_size) {
    const float* A = (const float*)d_in[0];
    const float* B = (const float*)d_in[1];
    int N = in_sizes[0];

    double n1 = (double)N - 1.0;
    double p01 = 0.01 * n1, p99 = 0.99 * n1;
    unsigned k01 = (unsigned)p01, k99 = (unsigned)p99;
    float f01 = (float)(p01 - (double)k01);
    float f99 = (float)(p99 - (double)k99);

    cudaFuncSetAttribute(k_fused, cudaFuncAttributeMaxDynamicSharedMemorySize, SMEM_BYTES);
    int bpsm = 0, sms = 0;
    cudaOccupancyMaxActiveBlocksPerMultiprocessor(&bpsm, k_fused, TPB, SMEM_BYTES);
    cudaDeviceGetAttribute(&sms, cudaDevAttrMultiProcessorCount, 0);
    if (bpsm < 1) bpsm = 1;
    long long grid = (long long)bpsm * (long long)sms;
    if (grid > 1024) grid = 1024;
    grid &= ~1LL;                      // even grid for the term split
    if (grid < 2) grid = 2;

    int n4 = N >> 2;
    long long halfT = (grid / 2) * TPB;
    int iters = (int)((n4 + halfT - 1) / halfT);
    int epb = iters * 4 + 8;           // per-thread elements in the split Parzen pass
    int reg = BUFSZ / (int)grid;       // per-block candidate region

    k_fused<<<(int)grid, TPB, SMEM_BYTES>>>(A, B, N, k01, k99, f01, f99, epb, reg, (float*)d_out);
}

// round 16
// speedup vs baseline: 1.4373x; 1.4373x over previous
#include <cuda_runtime.h>
#include <math.h>

#define NB 32
static constexpr int TPB   = 128;
static constexpr int PSLOT = 36;                      // padded bins (-2..33) one term
static constexpr int SMEM_BYTES = PSLOT * TPB * 8;    // 36864
static constexpr int BUFSZ = 1 << 22;                 // candidate buffer entries per array

// ---------------- radix-select state ----------------
struct QS { unsigned pref[2][4]; unsigned rank[2][4]; unsigned key[2][4]; };
__device__ QS g_qs;
__device__ int g_hist[2][4][256];
__device__ unsigned g_bufA[BUFSZ];
__device__ unsigned g_bufB[BUFSZ];

struct TermP {
    float flo, fhi, mlo, mhi, t0, is, QhSW, Q9SW, SXoSW;
    float ac[7], cc[5], sc[5];
    double SXinv, SSX, SSXX, SSXinv, SSXXinv;
};
struct Params { TermP tp[2]; float SW; double SWinv; };
__device__ Params g_p;

// exact global accumulators (integer atomics -> deterministic)
__device__ unsigned long long g_accH[64];
__device__ unsigned long long g_accL[64];
__device__ unsigned long long g_accS[4];

// ---------------- grid barrier (sense reversing) ----------------
__device__ unsigned g_arrive = 0;
__device__ unsigned g_gen = 0;

__device__ __forceinline__ void gridbar() {
    __threadfence();
    __syncthreads();
    if (threadIdx.x == 0) {
        unsigned gen = *(volatile unsigned*)&g_gen;
        unsigned prev = atomicAdd(&g_arrive, 1u);
        if (prev == gridDim.x - 1u) {
            g_arrive = 0u;
            __threadfence();
            *(volatile unsigned*)&g_gen = gen + 1u;
        } else {
            while (*(volatile unsigned*)&g_gen == gen) __nanosleep(64);
        }
        __threadfence();
    }
    __syncthreads();
}

__device__ __forceinline__ unsigned f2key(float f) {
    unsigned u = __float_as_uint(f);
    return (u & 0x80000000u) ? ~u : (u | 0x80000000u);
}
__device__ __forceinline__ float key2f(unsigned k) {
    unsigned u = (k & 0x80000000u) ? (k & 0x7FFFFFFFu) : ~k;
    return __uint_as_float(u);
}

// ws is already weight*SW; xr = x*SX/SW so lw = w*x*SX
__device__ __forceinline__ unsigned long long pack2s(float ws, float xr) {
    unsigned hw = __float2uint_rn(ws);
    int lw = __float2int_rn(ws * xr);
    return ((unsigned long long)hw << 32) + (unsigned long long)(long long)lw;
}

// ---------------- one-term Parzen pass (4-bin window, prefetch, trimmed polys) ----
__device__ __forceinline__ void parzen_pass(
    const float4* __restrict__ Y4, const float4* __restrict__ X4,
    const float* __restrict__ Ys, const float* __restrict__ Xs,
    int term, int N, int N4, int gid, int gsz,
    unsigned long long* priv)
{
    __shared__ float s_red[2][TPB / 32];
    int t = threadIdx.x;
    const TermP* tg = &g_p.tp[term];
    float flo = tg->flo, fhi = tg->fhi, mlo = tg->mlo, mhi = tg->mhi;
    float t0 = tg->t0, is = tg->is;
    float QhSW = tg->QhSW, Q9SW = tg->Q9SW, SXoSW = tg->SXoSW;
    float ac[7], cc[5], sc[5];
    #pragma unroll
    for (int k = 0; k < 7; k++) ac[k] = tg->ac[k];
    #pragma unroll
    for (int k = 0; k < 5; k++) { cc[k] = tg->cc[k]; sc[k] = tg->sc[k]; }

    #pragma unroll
    for (int s = 0; s < PSLOT; s++) priv[s * TPB + t] = 0ull;
    __syncthreads();

    unsigned long long* col = priv + t;
    float sx = 0.f, sxx = 0.f;

    // software-pipelined main loop: prefetch next iteration's float4 pair
    int i = gid;
    bool valid = (i < N4);
    float4 y4, x4;
    if (valid) { y4 = Y4[i]; x4 = X4[i]; }
    while (valid) {
        int inext = i + gsz;
        bool vnext = (inext < N4);
        float4 yn = y4, xn = x4;
        if (vnext) { yn = Y4[inext]; xn = X4[inext]; }

        float ye[4] = {y4.x, y4.y, y4.z, y4.w};
        float xe[4] = {x4.x, x4.y, x4.z, x4.w};
        #pragma unroll
        for (int e = 0; e < 4; e++) {
            float y = fminf(fmaxf(ye[e], flo), fhi);
            float x = fminf(fmaxf(xe[e], mlo), mhi);
            sx += x; sxx = fmaf(x, x, sxx);
            float g = (y - t0) * is;              // in [-0.5, 31.5]
            float rf = floorf(g);
            int r = (int)rf;
            r = min(max(r, -1), NB - 1);          // hard in-bounds
            float v = (g - rf) - 0.5f;            // in [-0.5, 0.5]
            float s = v * v;
            float Av = ac[6];
            #pragma unroll
            for (int k = 5; k >= 0; k--) Av = fmaf(Av, s, ac[k]);   // e^{-c v^2}
            float C = cc[4];
            #pragma unroll
            for (int k = 3; k >= 0; k--) C = fmaf(C, s, cc[k]);     // cosh(c v)
            float Sp = sc[4];
            #pragma unroll
            for (int k = 3; k >= 0; k--) Sp = fmaf(Sp, s, sc[k]);   // sinh(c v)/v
            float S = Sp * v;
            float G = C + S, Gi = C - S;          // e^{+cv}, e^{-cv}
            float a1s = Av * QhSW, a9s = Av * Q9SW;   // SW folded in
            float xr = x * SXoSW;
            float Gi2 = Gi * Gi, G2 = G * G;
            unsigned long long* p = col + (unsigned)(r + 1) * (unsigned)TPB;
            p[0]       = p[0]       + pack2s(a9s * (Gi * Gi2), xr);  // bin r-1
            p[TPB]     = p[TPB]     + pack2s(a1s * Gi, xr);          // bin r
            p[2 * TPB] = p[2 * TPB] + pack2s(a1s * G, xr);           // bin r+1
            p[3 * TPB] = p[3 * TPB] + pack2s(a9s * (G * G2), xr);    // bin r+2
        }
        y4 = yn; x4 = xn; i = inext; valid = vnext;
    }
    if (gid == 0) {
        for (int rr = N4 << 2; rr < N; rr++) {
            float y = fminf(fmaxf(Ys[rr], flo), fhi);
            float x = fminf(fmaxf(Xs[rr], mlo), mhi);
            sx += x; sxx = fmaf(x, x, sxx);
            float g = (y - t0) * is;
            float rf = floorf(g);
            int r = (int)rf;
            r = min(max(r, -1), NB - 1);
            float v = (g - rf) - 0.5f;
            float s = v * v;
            float Av = ac[6];
            for (int k = 5; k >= 0; k--) Av = fmaf(Av, s, ac[k]);
            float C = cc[4];
            for (int k = 3; k >= 0; k--) C = fmaf(C, s, cc[k]);
            float Sp = sc[4];
            for (int k = 3; k >= 0; k--) Sp = fmaf(Sp, s, sc[k]);
            float S = Sp * v;
            float G = C + S, Gi = C - S;
            float a1s = Av * QhSW, a9s = Av * Q9SW;
            float xr = x * SXoSW;
            unsigned long long* p = col + (unsigned)(r + 1) * (unsigned)TPB;
            p[0]       = p[0]       + pack2s(a9s * (Gi * Gi * Gi), xr);
            p[TPB]     = p[TPB]     + pack2s(a1s * Gi, xr);
            p[2 * TPB] = p[2 * TPB] + pack2s(a1s * G, xr);
            p[3 * TPB] = p[3 * TPB] + pack2s(a9s * (G * G * G), xr);
        }
    }

    int lane = t & 31, warp = t >> 5;
    #pragma unroll
    for (int off = 16; off; off >>= 1) {
        sx  += __shfl_down_sync(0xFFFFFFFFu, sx,  off);
        sxx += __shfl_down_sync(0xFFFFFFFFu, sxx, off);
    }
    if (lane == 0) { s_red[0][warp] = sx; s_red[1][warp] = sxx; }
    __syncthreads();   // orders priv writes + s_red

    if (t < NB) {
        unsigned long long H = 0; long long L = 0;
        #pragma unroll 4
        for (int jj = 0; jj < TPB; jj++) {
            int j = (jj + t) & (TPB - 1);
            unsigned long long v = priv[(t + 2) * TPB + j];
            int lo = (int)(unsigned)v;
            unsigned hi = (unsigned)(v >> 32) + ((lo < 0) ? 1u : 0u);
            H += hi; L += lo;
        }
        atomicAdd(&g_accH[term * NB + t], H);
        atomicAdd(&g_accL[term * NB + t], (unsigned long long)L);
    }
    if (t == 0) {
        double bsx = 0.0, bsxx = 0.0;
        #pragma unroll
        for (int w = 0; w < TPB / 32; w++) { bsx += (double)s_red[0][w]; bsxx += (double)s_red[1][w]; }
        long long v1 = __double2ll_rn(bsx * tg->SSX);
        long long v2 = __double2ll_rn(bsxx * tg->SSXX);
        atomicAdd(&g_accS[term * 2 + 0], (unsigned long long)v1);
        atomicAdd(&g_accS[term * 2 + 1], (unsigned long long)v2);
    }
    __syncthreads();
}

__global__ void __launch_bounds__(TPB, 6)
k_fused(const float* __restrict__ A, const float* __restrict__ B, int N,
        unsigned k01, unsigned k99, float f01, float f99, int epb, int reg,
        float* __restrict__ out)
{
    extern __shared__ unsigned long long dyn[];
    unsigned long long* priv = dyn;
    int* shist = (int*)dyn;
    __shared__ int s_cntA, s_cntB;

    int t = threadIdx.x;
    int nb = gridDim.x;
    int gsz = nb * TPB;
    int gid = blockIdx.x * TPB + t;
    const float4* A4 = (const float4*)A;
    const float4* B4 = (const float4*)B;
    int N4 = N >> 2;

    if (blockIdx.x == 0) {
        if (t < 8) {
            int a = t >> 2, j = t & 3;
            g_qs.pref[a][j] = 0u;
            g_qs.rank[a][j] = (j < 2 ? k01 : k99) + (unsigned)(j & 1);
        }
        for (int i = t; i < 64; i += TPB) { g_accH[i] = 0ull; g_accL[i] = 0ull; }
        if (t < 4) g_accS[t] = 0ull;
    }

    // ================= quantile phase: 4 radix passes =================
    for (int pass = 0; pass < 4; pass++) {
        for (int i = t; i < 2048; i += TPB) shist[i] = 0;
        if (pass == 1 && t == 0) { s_cntA = 0; s_cntB = 0; }
        __syncthreads();
        if (pass == 0) {
            int ca = (t & 3) * 256, cb = (4 + (t & 3)) * 256;
            for (int i = gid; i < N4; i += gsz) {
                float4 va = A4[i], vb = B4[i];
                atomicAdd(&shist[ca + (f2key(va.x) >> 24)], 1);
                atomicAdd(&shist[ca + (f2key(va.y) >> 24)], 1);
                atomicAdd(&shist[ca + (f2key(va.z) >> 24)], 1);
                atomicAdd(&shist[ca + (f2key(va.w) >> 24)], 1);
                atomicAdd(&shist[cb + (f2key(vb.x) >> 24)], 1);
                atomicAdd(&shist[cb + (f2key(vb.y) >> 24)], 1);
                atomicAdd(&shist[cb + (f2key(vb.z) >> 24)], 1);
                atomicAdd(&shist[cb + (f2key(vb.w) >> 24)], 1);
            }
            if (gid == 0) {
                for (int r = N4 << 2; r < N; r++) {
                    atomicAdd(&shist[0 * 256 + (f2key(A[r]) >> 24)], 1);
                    atomicAdd(&shist[4 * 256 + (f2key(B[r]) >> 24)], 1);
                }
            }
        } else if (pass == 1) {
            unsigned pa[4], pb[4];
            #pragma unroll
            for (int j = 0; j < 4; j++) { pa[j] = g_qs.pref[0][j]; pb[j] = g_qs.pref[1][j]; }
            unsigned baseA = (unsigned)blockIdx.x * (unsigned)reg;
            unsigned baseB = baseA;
            for (int i = gid; i < N4; i += gsz) {
                float4 va = A4[i], vb = B4[i];
                float ea[4] = {va.x, va.y, va.z, va.w};
                float eb[4] = {vb.x, vb.y, vb.z, vb.w};
                #pragma unroll
                for (int e = 0; e < 4; e++) {
                    unsigned k = f2key(ea[e]);
                    unsigned top = k >> 24, b = (k >> 16) & 255u;
                    bool m = false;
                    #pragma unroll
                    for (int j = 0; j < 4; j++)
                        if (top == pa[j]) { atomicAdd(&shist[j * 256 + b], 1); m = true; }
                    if (m) {
                        int pos = atomicAdd(&s_cntA, 1);
                        if (pos < reg) g_bufA[baseA + pos] = k;
                    }
                    k = f2key(eb[e]);
                    top = k >> 24; b = (k >> 16) & 255u;
                    m = false;
                    #pragma unroll
                    for (int j = 0; j < 4; j++)
                        if (top == pb[j]) { atomicAdd(&shist[(4 + j) * 256 + b], 1); m = true; }
                    if (m) {
                        int pos = atomicAdd(&s_cntB, 1);
                        if (pos < reg) g_bufB[baseB + pos] = k;
                    }
                }
            }
            if (gid == 0) {
                for (int r = N4 << 2; r < N; r++) {
                    unsigned k = f2key(A[r]);
                    unsigned top = k >> 24, b = (k >> 16) & 255u;
                    bool m = false;
                    for (int j = 0; j < 4; j++)
                        if (top == pa[j]) { atomicAdd(&shist[j * 256 + b], 1); m = true; }
                    if (m) {
                        int pos = atomicAdd(&s_cntA, 1);
                        if (pos < reg) g_bufA[baseA + pos] = k;
                    }
                    k = f2key(B[r]); top = k >> 24; b = (k >> 16) & 255u;
                    m = false;
                    for (int j = 0; j < 4; j++)
                        if (top == pb[j]) { atomicAdd(&shist[(4 + j) * 256 + b], 1); m = true; }
                    if (m) {
                        int pos = atomicAdd(&s_cntB, 1);
                        if (pos < reg) g_bufB[baseB + pos] = k;
                    }
                }
            }
        } else {
            // passes 2,3: scan only this block's compacted candidates
            unsigned pa[4], pb[4];
            #pragma unroll
            for (int j = 0; j < 4; j++) { pa[j] = g_qs.pref[0][j]; pb[j] = g_qs.pref[1][j]; }
            int ms = 32 - 8 * pass, bs = 24 - 8 * pass;
            unsigned baseA = (unsigned)blockIdx.x * (unsigned)reg;
            int cntA = min(s_cntA, reg), cntB = min(s_cntB, reg);
            for (int i = t; i < cntA; i += TPB) {
                unsigned k = g_bufA[baseA + i];
                unsigned top = k >> ms, b = (k >> bs) & 255u;
                #pragma unroll
                for (int j = 0; j < 4; j++)
                    if (top == pa[j]) atomicAdd(&shist[j * 256 + b], 1);
            }
            for (int i = t; i < cntB; i += TPB) {
                unsigned k = g_bufB[baseA + i];
                unsigned top = k >> ms, b = (k >> bs) & 255u;
                #pragma unroll
                for (int j = 0; j < 4; j++)
                    if (top == pb[j]) atomicAdd(&shist[(4 + j) * 256 + b], 1);
            }
        }
        __syncthreads();
        for (int i = t; i < 2048; i += TPB) {
            int v = shist[i];
            if (v) {
                int row = i >> 8, bin = i & 255;
                int a = row >> 2;
                int j = (pass == 0) ? 0 : (row & 3);
                atomicAdd(&g_hist[a][j][bin], v);
            }
        }
        gridbar();

        if (blockIdx.x == 0) {
            int warp = t >> 5, lane = t & 31;
            for (int q = warp; q < 8; q += 4) {
                int a = q >> 2, jj = q & 3;
                int jsel = (pass == 0) ? 0 : jj;
                const int* h = &g_hist[a][jsel][0];
                int c[8]; int ps = 0;
                #pragma unroll
                for (int k = 0; k < 8; k++) { c[k] = h[lane * 8 + k]; ps += c[k]; }
                int v = ps;
                #pragma unroll
                for (int off = 1; off < 32; off <<= 1) {
                    int n = __shfl_up_sync(0xFFFFFFFFu, v, off);
                    if (lane >= off) v += n;
                }
                unsigned excl = (unsigned)(v - ps);
                unsigned rank = g_qs.rank[a][jj];
                bool has = (rank >= excl) && (rank < excl + (unsigned)ps);
                if (has) {
                    unsigned cum = excl; int d = 0;
                    #pragma unroll
                    for (int k = 0; k < 8; k++) {
                        if (cum + (unsigned)c[k] > rank) { d = k; break; }
                        cum += (unsigned)c[k];
                    }
                    unsigned np = (g_qs.pref[a][jj] << 8) | (unsigned)(lane * 8 + d);
                    g_qs.pref[a][jj] = np;
                    g_qs.rank[a][jj] = rank - cum;
                    if (pass == 3) g_qs.key[a][jj] = np;
                }
            }
            __syncthreads();
            for (int i = t; i < 2048; i += TPB) (&g_hist[0][0][0])[i] = 0;
            if (pass == 3 && t == 0) {
                float q[2][2];
                for (int a = 0; a < 2; a++) {
                    float v0 = key2f(g_qs.key[a][0]), v1 = key2f(g_qs.key[a][1]);
                    q[a][0] = v0 + f01 * (v1 - v0);
                    v0 = key2f(g_qs.key[a][2]); v1 = key2f(g_qs.key[a][3]);
                    q[a][1] = v0 + f99 * (v1 - v0);
                }
                const float sigma_ratio = (float)(1.0 / 2.355);
                float swf = exp2f(floorf(log2f(1073741824.0f / (float)epb)));
                g_p.SW = swf; g_p.SWinv = 1.0 / (double)swf;
                for (int term = 0; term < 2; term++) {
                    TermP& tp = g_p.tp[term];
                    int pa2 = term, ta2 = 1 - term;
                    float flo = q[ta2][0], fhi = q[ta2][1];
                    tp.flo = flo; tp.fhi = fhi;
                    tp.mlo = q[pa2][0]; tp.mhi = q[pa2][1];
                    float fb = (fhi - flo) / (float)NB;
                    float lo = flo + 0.5f * fb, hi = fhi - 0.5f * fb;
                    float step = (hi - lo) / (float)(NB - 1);
                    float sd = 0.f, prev = lo;
                    for (int i = 1; i < NB; i++) { float v = lo + step * (float)i; sd += v - prev; prev = v; }
                    float fs = (sd / (float)(NB - 1)) * sigma_ratio;
                    float preterm = 1.0f / (2.0f * fs * fs);
                    tp.t0 = lo; tp.is = 1.0f / step;
                    double c = (double)preterm * (double)step * (double)step;
                    // trimmed series: exp(-c s) deg-6, cosh/sinh 4 extra terms
                    double a = 1.0; tp.ac[0] = 1.0f;
                    for (int k = 1; k <= 6; k++) { a *= (-c) / (double)k; tp.ac[k] = (float)a; }
                    double X = c * c;
                    double tm = 1.0; tp.cc[0] = 1.0f;
                    for (int m = 1; m <= 4; m++) { tm *= X / ((double)(2 * m - 1) * (double)(2 * m)); tp.cc[m] = (float)tm; }
                    double st = c; tp.sc[0] = (float)c;
                    for (int m = 1; m <= 4; m++) { st *= X / ((double)(2 * m) * (double)(2 * m + 1)); tp.sc[m] = (float)st; }
                    double Qh = exp(-0.25 * c), Qh9 = exp(-2.25 * c);
                    tp.QhSW = (float)(Qh * (double)swf);
                    tp.Q9SW = (float)(Qh9 * (double)swf);
                    float xm = fmaxf(fabsf(tp.mlo), fabsf(tp.mhi));
                    if (xm < 1e-20f) xm = 1e-20f;
                    float sxs = exp2f(floorf(log2f(1073741824.0f / ((float)epb * xm))));
                    tp.SXoSW = sxs / swf;            // exact (both powers of 2)
                    tp.SXinv = 1.0 / (double)sxs;
                    double nx = (double)N * (double)xm;
                    tp.SSX = exp2(floor(log2(2.3e18 / nx)));
                    tp.SSXinv = 1.0 / tp.SSX;
                    double nxx = nx * (double)xm;
                    tp.SSXX = exp2(floor(log2(2.3e18 / nxx)));
                    tp.SSXXinv = 1.0 / tp.SSXX;
                }
            }
        }
        gridbar();
    }

    // ====== Parzen phase: ONE pass, terms split across blocks by parity ======
    {
        int term = blockIdx.x & 1;
        int gid2 = (blockIdx.x >> 1) * TPB + t;
        int gsz2 = (nb >> 1) * TPB;
        if (term == 0)
            parzen_pass(B4, A4, B, A, 0, N, N4, gid2, gsz2, priv);   // target=B, pred=A
        else
            parzen_pass(A4, B4, A, B, 1, N, N4, gid2, gsz2, priv);   // target=A, pred=B
    }
    gridbar();

    // ================= final (block 0) =================
    if (blockIdx.x == 0) {
        unsigned long long* stage = dyn;   // [0..63]=H, [64..127]=L, [128..131]=S
        if (t < 64) { stage[t] = g_accH[t]; stage[64 + t] = g_accL[t]; }
        if (t >= 64 && t < 68) stage[128 + (t - 64)] = g_accS[t - 64];
        __syncthreads();
        if (t == 0) {
            const double eps = 1.1920928955078125e-07;
            double dN = (double)N;
            double swi = g_p.SWinv;
            double eta = 0.0;
            for (int term = 0; term < 2; term++) {
                double sxi = g_p.tp[term].SXinv;
                double sx  = (double)(long long)stage[128 + 2 * term]     * g_p.tp[term].SSXinv;
                double sxx = (double)(long long)stage[128 + 2 * term + 1] * g_p.tp[term].SSXXinv;
                double mean = sx / dN;
                double Ssw = 0.0, num = 0.0;
                for (int j = 0; j < NB; j++) {
                    double sw  = (double)stage[term * NB + j] * swi;
                    double swx = (double)(long long)stage[64 + term * NB + j] * sxi;
                    double m = swx / (sw + eps);
                    double d = m - mean;
                    num += sw * d * d;
                    Ssw += sw;
                }
                double bgv = num / (Ssw + eps);
                double var = (sxx - sx * sx / dN) / (dN - 1.0);
                eta += bgv / (var + eps);
            }
            out[0] = (float)(-0.5 * eta);
        }
    }
}

extern "C" void kernel_launch(void* const* d_in, const int* in_sizes, int n_in,
                              void* d_out, int out_size) {
    const float* A = (const float*)d_in[0];
    const float* B = (const float*)d_in[1];
    int N = in_sizes[0];

    double n1 = (double)N - 1.0;
    double p01 = 0.01 * n1, p99 = 0.99 * n1;
    unsigned k01 = (unsigned)p01, k99 = (unsigned)p99;
    float f01 = (float)(p01 - (double)k01);
    float f99 = (float)(p99 - (double)k99);

    cudaFuncSetAttribute(k_fused, cudaFuncAttributeMaxDynamicSharedMemorySize, SMEM_BYTES);
    int bpsm = 0, sms = 0;
    cudaOccupancyMaxActiveBlocksPerMultiprocessor(&bpsm, k_fused, TPB, SMEM_BYTES);
    cudaDeviceGetAttribute(&sms, cudaDevAttrMultiProcessorCount, 0);
    if (bpsm < 1) bpsm = 1;
    long long grid = (long long)bpsm * (long long)sms;
    if (grid > 1024) grid = 1024;
    grid &= ~1LL;                      // even grid for the term split
    if (grid < 2) grid = 2;

    int n4 = N >> 2;
    long long halfT = (grid / 2) * TPB;
    int iters = (int)((n4 + halfT - 1) / halfT);
    int epb = iters * 4 + 8;           // per-thread elements in the split Parzen pass
    int reg = BUFSZ / (int)grid;       // per-block candidate region

    k_fused<<<(int)grid, TPB, SMEM_BYTES>>>(A, B, N, k01, k99, f01, f99, epb, reg, (float*)d_out);
}

// round 17
// speedup vs baseline: 1.4429x; 1.0039x over previous
#include <cuda_runtime.h>
#include <math.h>

#define NB 32
static constexpr int TPB   = 128;
static constexpr int PSLOT = 34;                      // padded bins (-1..32) one term
static constexpr int SMEM_BYTES = PSLOT * TPB * 8;    // 34816
static constexpr int BUFSZ = 1 << 22;                 // candidate buffer entries per array

// ---------------- radix-select state ----------------
struct QS { unsigned pref[2][4]; unsigned rank[2][4]; unsigned key[2][4]; };
__device__ QS g_qs;
__device__ int g_hist[2][4][256];
__device__ unsigned g_bufA[BUFSZ];
__device__ unsigned g_bufB[BUFSZ];

struct TermP {
    float flo, fhi, mlo, mhi, t0, is, QSW, SWf, SXoSW;
    float ac[7], cc[5], sc[5];
    double SXinv, SSX, SSXX, SSXinv, SSXXinv;
};
struct Params { TermP tp[2]; float SW; double SWinv; };
__device__ Params g_p;

// exact global accumulators (integer atomics -> deterministic)
__device__ unsigned long long g_accH[64];
__device__ unsigned long long g_accL[64];
__device__ unsigned long long g_accS[4];

// ---------------- grid barrier (sense reversing) ----------------
__device__ unsigned g_arrive = 0;
__device__ unsigned g_gen = 0;

__device__ __forceinline__ void gridbar() {
    __threadfence();
    __syncthreads();
    if (threadIdx.x == 0) {
        unsigned gen = *(volatile unsigned*)&g_gen;
        unsigned prev = atomicAdd(&g_arrive, 1u);
        if (prev == gridDim.x - 1u) {
            g_arrive = 0u;
            __threadfence();
            *(volatile unsigned*)&g_gen = gen + 1u;
        } else {
            while (*(volatile unsigned*)&g_gen == gen) __nanosleep(64);
        }
        __threadfence();
    }
    __syncthreads();
}

__device__ __forceinline__ unsigned f2key(float f) {
    unsigned u = __float_as_uint(f);
    return (u & 0x80000000u) ? ~u : (u | 0x80000000u);
}
__device__ __forceinline__ float key2f(unsigned k) {
    unsigned u = (k & 0x80000000u) ? (k & 0x7FFFFFFFu) : ~k;
    return __uint_as_float(u);
}

// ws is already weight*SW; xr = x*SX/SW so lw = w*x*SX
__device__ __forceinline__ unsigned long long pack2s(float ws, float xr) {
    unsigned hw = __float2uint_rn(ws);
    int lw = __float2int_rn(ws * xr);
    return ((unsigned long long)hw << 32) + (unsigned long long)(long long)lw;
}

// ---------------- one-term Parzen pass (3-bin window, prefetch) ----------------
__device__ __forceinline__ void parzen_pass(
    const float4* __restrict__ Y4, const float4* __restrict__ X4,
    const float* __restrict__ Ys, const float* __restrict__ Xs,
    int term, int N, int N4, int gid, int gsz,
    unsigned long long* priv)
{
    __shared__ float s_red[2][TPB / 32];
    int t = threadIdx.x;
    const TermP* tg = &g_p.tp[term];
    float flo = tg->flo, fhi = tg->fhi, mlo = tg->mlo, mhi = tg->mhi;
    float t0 = tg->t0, is = tg->is;
    float QSW = tg->QSW, SWf = tg->SWf, SXoSW = tg->SXoSW;
    float ac[7], cc[5], sc[5];
    #pragma unroll
    for (int k = 0; k < 7; k++) ac[k] = tg->ac[k];
    #pragma unroll
    for (int k = 0; k < 5; k++) { cc[k] = tg->cc[k]; sc[k] = tg->sc[k]; }

    #pragma unroll
    for (int s = 0; s < PSLOT; s++) priv[s * TPB + t] = 0ull;
    __syncthreads();

    unsigned long long* col = priv + t;
    float sx = 0.f, sxx = 0.f;

    // software-pipelined main loop: prefetch next iteration's float4 pair
    int i = gid;
    bool valid = (i < N4);
    float4 y4, x4;
    if (valid) { y4 = Y4[i]; x4 = X4[i]; }
    while (valid) {
        int inext = i + gsz;
        bool vnext = (inext < N4);
        float4 yn = y4, xn = x4;
        if (vnext) { yn = Y4[inext]; xn = X4[inext]; }

        float ye[4] = {y4.x, y4.y, y4.z, y4.w};
        float xe[4] = {x4.x, x4.y, x4.z, x4.w};
        #pragma unroll
        for (int e = 0; e < 4; e++) {
            float y = fminf(fmaxf(ye[e], flo), fhi);
            float x = fminf(fmaxf(xe[e], mlo), mhi);
            sx += x; sxx = fmaf(x, x, sxx);
            float g = (y - t0) * is;                  // in [-0.5, 31.5]
            float rf = floorf(g + 0.5f);              // round to nearest bin
            rf = fminf(fmaxf(rf, 0.0f), 31.0f);       // clamp (exact float int)
            int b0 = (int)rf;                         // in [0, 31]
            float v = g - rf;                         // in [-0.5, 0.5]
            float s = v * v;
            float Av = ac[6];
            #pragma unroll
            for (int k = 5; k >= 0; k--) Av = fmaf(Av, s, ac[k]);   // e^{-c v^2}
            float C = cc[4];
            #pragma unroll
            for (int k = 3; k >= 0; k--) C = fmaf(C, s, cc[k]);     // cosh(c v)
            float Sp = sc[4];
            #pragma unroll
            for (int k = 3; k >= 0; k--) Sp = fmaf(Sp, s, sc[k]);   // sinh(c v)/v
            float S = Sp * v;
            float G = C + S, Gi = C - S;              // e^{+cv}, e^{-cv}
            float E = G * G, Ei = Gi * Gi;            // e^{+2cv}, e^{-2cv}
            float AQ = Av * QSW;                      // A * e^{-c} * SW
            float As = Av * SWf;                      // A * SW (center)
            float xr = x * SXoSW;
            unsigned long long* p = col + (unsigned)b0 * (unsigned)TPB;
            p[0]       = p[0]       + pack2s(AQ * Ei, xr);   // bin b0-1
            p[TPB]     = p[TPB]     + pack2s(As, xr);        // bin b0
            p[2 * TPB] = p[2 * TPB] + pack2s(AQ * E, xr);    // bin b0+1
        }
        y4 = yn; x4 = xn; i = inext; valid = vnext;
    }
    if (gid == 0) {
        for (int rr = N4 << 2; rr < N; rr++) {
            float y = fminf(fmaxf(Ys[rr], flo), fhi);
            float x = fminf(fmaxf(Xs[rr], mlo), mhi);
            sx += x; sxx = fmaf(x, x, sxx);
            float g = (y - t0) * is;
            float rf = floorf(g + 0.5f);
            rf = fminf(fmaxf(rf, 0.0f), 31.0f);
            int b0 = (int)rf;
            float v = g - rf;
            float s = v * v;
            float Av = ac[6];
            for (int k = 5; k >= 0; k--) Av = fmaf(Av, s, ac[k]);
            float C = cc[4];
            for (int k = 3; k >= 0; k--) C = fmaf(C, s, cc[k]);
            float Sp = sc[4];
            for (int k = 3; k >= 0; k--) Sp = fmaf(Sp, s, sc[k]);
            float S = Sp * v;
            float G = C + S, Gi = C - S;
            float E = G * G, Ei = Gi * Gi;
            float AQ = Av * QSW;
            float As = Av * SWf;
            float xr = x * SXoSW;
            unsigned long long* p = col + (unsigned)b0 * (unsigned)TPB;
            p[0]       = p[0]       + pack2s(AQ * Ei, xr);
            p[TPB]     = p[TPB]     + pack2s(As, xr);
            p[2 * TPB] = p[2 * TPB] + pack2s(AQ * E, xr);
        }
    }

    int lane = t & 31, warp = t >> 5;
    #pragma unroll
    for (int off = 16; off; off >>= 1) {
        sx  += __shfl_down_sync(0xFFFFFFFFu, sx,  off);
        sxx += __shfl_down_sync(0xFFFFFFFFu, sxx, off);
    }
    if (lane == 0) { s_red[0][warp] = sx; s_red[1][warp] = sxx; }
    __syncthreads();   // orders priv writes + s_red

    if (t < NB) {
        unsigned long long H = 0; long long L = 0;
        #pragma unroll 4
        for (int jj = 0; jj < TPB; jj++) {
            int j = (jj + t) & (TPB - 1);
            unsigned long long v = priv[(t + 1) * TPB + j];   // bin t at row t+1
            int lo = (int)(unsigned)v;
            unsigned hi = (unsigned)(v >> 32) + ((lo < 0) ? 1u : 0u);
            H += hi; L += lo;
        }
        atomicAdd(&g_accH[term * NB + t], H);
        atomicAdd(&g_accL[term * NB + t], (unsigned long long)L);
    }
    if (t == 0) {
        double bsx = 0.0, bsxx = 0.0;
        #pragma unroll
        for (int w = 0; w < TPB / 32; w++) { bsx += (double)s_red[0][w]; bsxx += (double)s_red[1][w]; }
        long long v1 = __double2ll_rn(bsx * tg->SSX);
        long long v2 = __double2ll_rn(bsxx * tg->SSXX);
        atomicAdd(&g_accS[term * 2 + 0], (unsigned long long)v1);
        atomicAdd(&g_accS[term * 2 + 1], (unsigned long long)v2);
    }
    __syncthreads();
}

__global__ void __launch_bounds__(TPB, 6)
k_fused(const float* __restrict__ A, const float* __restrict__ B, int N,
        unsigned k01, unsigned k99, float f01, float f99, int epb, int reg,
        float* __restrict__ out)
{
    extern __shared__ unsigned long long dyn[];
    unsigned long long* priv = dyn;
    int* shist = (int*)dyn;
    __shared__ int s_cntA, s_cntB;

    int t = threadIdx.x;
    int nb = gridDim.x;
    int gsz = nb * TPB;
    int gid = blockIdx.x * TPB + t;
    const float4* A4 = (const float4*)A;
    const float4* B4 = (const float4*)B;
    int N4 = N >> 2;

    if (blockIdx.x == 0) {
        if (t < 8) {
            int a = t >> 2, j = t & 3;
            g_qs.pref[a][j] = 0u;
            g_qs.rank[a][j] = (j < 2 ? k01 : k99) + (unsigned)(j & 1);
        }
        for (int i = t; i < 64; i += TPB) { g_accH[i] = 0ull; g_accL[i] = 0ull; }
        if (t < 4) g_accS[t] = 0ull;
    }

    // ================= quantile phase: 4 radix passes =================
    for (int pass = 0; pass < 4; pass++) {
        for (int i = t; i < 2048; i += TPB) shist[i] = 0;
        if (pass == 1 && t == 0) { s_cntA = 0; s_cntB = 0; }
        __syncthreads();
        if (pass == 0) {
            int ca = (t & 3) * 256, cb = (4 + (t & 3)) * 256;
            for (int i = gid; i < N4; i += gsz) {
                float4 va = A4[i], vb = B4[i];
                atomicAdd(&shist[ca + (f2key(va.x) >> 24)], 1);
                atomicAdd(&shist[ca + (f2key(va.y) >> 24)], 1);
                atomicAdd(&shist[ca + (f2key(va.z) >> 24)], 1);
                atomicAdd(&shist[ca + (f2key(va.w) >> 24)], 1);
                atomicAdd(&shist[cb + (f2key(vb.x) >> 24)], 1);
                atomicAdd(&shist[cb + (f2key(vb.y) >> 24)], 1);
                atomicAdd(&shist[cb + (f2key(vb.z) >> 24)], 1);
                atomicAdd(&shist[cb + (f2key(vb.w) >> 24)], 1);
            }
            if (gid == 0) {
                for (int r = N4 << 2; r < N; r++) {
                    atomicAdd(&shist[0 * 256 + (f2key(A[r]) >> 24)], 1);
                    atomicAdd(&shist[4 * 256 + (f2key(B[r]) >> 24)], 1);
                }
            }
        } else if (pass == 1) {
            unsigned pa[4], pb[4];
            #pragma unroll
            for (int j = 0; j < 4; j++) { pa[j] = g_qs.pref[0][j]; pb[j] = g_qs.pref[1][j]; }
            unsigned baseA = (unsigned)blockIdx.x * (unsigned)reg;
            unsigned baseB = baseA;
            for (int i = gid; i < N4; i += gsz) {
                float4 va = A4[i], vb = B4[i];
                float ea[4] = {va.x, va.y, va.z, va.w};
                float eb[4] = {vb.x, vb.y, vb.z, vb.w};
                #pragma unroll
                for (int e = 0; e < 4; e++) {
                    unsigned k = f2key(ea[e]);
                    unsigned top = k >> 24, b = (k >> 16) & 255u;
                    bool m = false;
                    #pragma unroll
                    for (int j = 0; j < 4; j++)
                        if (top == pa[j]) { atomicAdd(&shist[j * 256 + b], 1); m = true; }
                    if (m) {
                        int pos = atomicAdd(&s_cntA, 1);
                        if (pos < reg) g_bufA[baseA + pos] = k;
                    }
                    k = f2key(eb[e]);
                    top = k >> 24; b = (k >> 16) & 255u;
                    m = false;
                    #pragma unroll
                    for (int j = 0; j < 4; j++)
                        if (top == pb[j]) { atomicAdd(&shist[(4 + j) * 256 + b], 1); m = true; }
                    if (m) {
                        int pos = atomicAdd(&s_cntB, 1);
                        if (pos < reg) g_bufB[baseB + pos] = k;
                    }
                }
            }
            if (gid == 0) {
                for (int r = N4 << 2; r < N; r++) {
                    unsigned k = f2key(A[r]);
                    unsigned top = k >> 24, b = (k >> 16) & 255u;
                    bool m = false;
                    for (int j = 0; j < 4; j++)
                        if (top == pa[j]) { atomicAdd(&shist[j * 256 + b], 1); m = true; }
                    if (m) {
                        int pos = atomicAdd(&s_cntA, 1);
                        if (pos < reg) g_bufA[baseA + pos] = k;
                    }
                    k = f2key(B[r]); top = k >> 24; b = (k >> 16) & 255u;
                    m = false;
                    for (int j = 0; j < 4; j++)
                        if (top == pb[j]) { atomicAdd(&shist[(4 + j) * 256 + b], 1); m = true; }
                    if (m) {
                        int pos = atomicAdd(&s_cntB, 1);
                        if (pos < reg) g_bufB[baseB + pos] = k;
                    }
                }
            }
        } else {
            // passes 2,3: scan only this block's compacted candidates
            unsigned pa[4], pb[4];
            #pragma unroll
            for (int j = 0; j < 4; j++) { pa[j] = g_qs.pref[0][j]; pb[j] = g_qs.pref[1][j]; }
            int ms = 32 - 8 * pass, bs = 24 - 8 * pass;
            unsigned baseA = (unsigned)blockIdx.x * (unsigned)reg;
            int cntA = min(s_cntA, reg), cntB = min(s_cntB, reg);
            for (int i = t; i < cntA; i += TPB) {
                unsigned k = g_bufA[baseA + i];
                unsigned top = k >> ms, b = (k >> bs) & 255u;
                #pragma unroll
                for (int j = 0; j < 4; j++)
                    if (top == pa[j]) atomicAdd(&shist[j * 256 + b], 1);
            }
            for (int i = t; i < cntB; i += TPB) {
                unsigned k = g_bufB[baseA + i];
                unsigned top = k >> ms, b = (k >> bs) & 255u;
                #pragma unroll
                for (int j = 0; j < 4; j++)
                    if (top == pb[j]) atomicAdd(&shist[(4 + j) * 256 + b], 1);
            }
        }
        __syncthreads();
        for (int i = t; i < 2048; i += TPB) {
            int v = shist[i];
            if (v) {
                int row = i >> 8, bin = i & 255;
                int a = row >> 2;
                int j = (pass == 0) ? 0 : (row & 3);
                atomicAdd(&g_hist[a][j][bin], v);
            }
        }
        gridbar();

        if (blockIdx.x == 0) {
            int warp = t >> 5, lane = t & 31;
            for (int q = warp; q < 8; q += 4) {
                int a = q >> 2, jj = q & 3;
                int jsel = (pass == 0) ? 0 : jj;
                const int* h = &g_hist[a][jsel][0];
                int c[8]; int ps = 0;
                #pragma unroll
                for (int k = 0; k < 8; k++) { c[k] = h[lane * 8 + k]; ps += c[k]; }
                int v = ps;
                #pragma unroll
                for (int off = 1; off < 32; off <<= 1) {
                    int n = __shfl_up_sync(0xFFFFFFFFu, v, off);
                    if (lane >= off) v += n;
                }
                unsigned excl = (unsigned)(v - ps);
                unsigned rank = g_qs.rank[a][jj];
                bool has = (rank >= excl) && (rank < excl + (unsigned)ps);
                if (has) {
                    unsigned cum = excl; int d = 0;
                    #pragma unroll
                    for (int k = 0; k < 8; k++) {
                        if (cum + (unsigned)c[k] > rank) { d = k; break; }
                        cum += (unsigned)c[k];
                    }
                    unsigned np = (g_qs.pref[a][jj] << 8) | (unsigned)(lane * 8 + d);
                    g_qs.pref[a][jj] = np;
                    g_qs.rank[a][jj] = rank - cum;
                    if (pass == 3) g_qs.key[a][jj] = np;
                }
            }
            __syncthreads();
            for (int i = t; i < 2048; i += TPB) (&g_hist[0][0][0])[i] = 0;
            if (pass == 3 && t == 0) {
                float q[2][2];
                for (int a = 0; a < 2; a++) {
                    float v0 = key2f(g_qs.key[a][0]), v1 = key2f(g_qs.key[a][1]);
                    q[a][0] = v0 + f01 * (v1 - v0);
                    v0 = key2f(g_qs.key[a][2]); v1 = key2f(g_qs.key[a][3]);
                    q[a][1] = v0 + f99 * (v1 - v0);
                }
                const float sigma_ratio = (float)(1.0 / 2.355);
                float swf = exp2f(floorf(log2f(1073741824.0f / (float)epb)));
                g_p.SW = swf; g_p.SWinv = 1.0 / (double)swf;
                for (int term = 0; term < 2; term++) {
                    TermP& tp = g_p.tp[term];
                    int pa2 = term, ta2 = 1 - term;
                    float flo = q[ta2][0], fhi = q[ta2][1];
                    tp.flo = flo; tp.fhi = fhi;
                    tp.mlo = q[pa2][0]; tp.mhi = q[pa2][1];
                    float fb = (fhi - flo) / (float)NB;
                    float lo = flo + 0.5f * fb, hi = fhi - 0.5f * fb;
                    float step = (hi - lo) / (float)(NB - 1);
                    float sd = 0.f, prev = lo;
                    for (int i = 1; i < NB; i++) { float v = lo + step * (float)i; sd += v - prev; prev = v; }
                    float fs = (sd / (float)(NB - 1)) * sigma_ratio;
                    float preterm = 1.0f / (2.0f * fs * fs);
                    tp.t0 = lo; tp.is = 1.0f / step;
                    double c = (double)preterm * (double)step * (double)step;
                    // series: exp(-c s) deg-6, cosh/sinh of (c v) 4 extra terms
                    double a = 1.0; tp.ac[0] = 1.0f;
                    for (int k = 1; k <= 6; k++) { a *= (-c) / (double)k; tp.ac[k] = (float)a; }
                    double X = c * c;
                    double tm = 1.0; tp.cc[0] = 1.0f;
                    for (int m = 1; m <= 4; m++) { tm *= X / ((double)(2 * m - 1) * (double)(2 * m)); tp.cc[m] = (float)tm; }
                    double st = c; tp.sc[0] = (float)c;
                    for (int m = 1; m <= 4; m++) { st *= X / ((double)(2 * m) * (double)(2 * m + 1)); tp.sc[m] = (float)st; }
                    tp.QSW = (float)(exp(-c) * (double)swf);   // e^{-c} * SW
                    tp.SWf = swf;
                    float xm = fmaxf(fabsf(tp.mlo), fabsf(tp.mhi));
                    if (xm < 1e-20f) xm = 1e-20f;
                    float sxs = exp2f(floorf(log2f(1073741824.0f / ((float)epb * xm))));
                    tp.SXoSW = sxs / swf;            // exact (both powers of 2)
                    tp.SXinv = 1.0 / (double)sxs;
                    double nx = (double)N * (double)xm;
                    tp.SSX = exp2(floor(log2(2.3e18 / nx)));
                    tp.SSXinv = 1.0 / tp.SSX;
                    double nxx = nx * (double)xm;
                    tp.SSXX = exp2(floor(log2(2.3e18 / nxx)));
                    tp.SSXXinv = 1.0 / tp.SSXX;
                }
            }
        }
        gridbar();
    }

    // ====== Parzen phase: ONE pass, terms split across blocks by parity ======
    {
        int term = blockIdx.x & 1;
        int gid2 = (blockIdx.x >> 1) * TPB + t;
        int gsz2 = (nb >> 1) * TPB;
        if (term == 0)
            parzen_pass(B4, A4, B, A, 0, N, N4, gid2, gsz2, priv);   // target=B, pred=A
        else
            parzen_pass(A4, B4, A, B, 1, N, N4, gid2, gsz2, priv);   // target=A, pred=B
    }
    gridbar();

    // ================= final (block 0) =================
    if (blockIdx.x == 0) {
        unsigned long long* stage = dyn;   // [0..63]=H, [64..127]=L, [128..131]=S
        if (t < 64) { stage[t] = g_accH[t]; stage[64 + t] = g_accL[t]; }
        if (t >= 64 && t < 68) stage[128 + (t - 64)] = g_accS[t - 64];
        __syncthreads();
        if (t == 0) {
            const double eps = 1.1920928955078125e-07;
            double dN = (double)N;
            double swi = g_p.SWinv;
            double eta = 0.0;
            for (int term = 0; term < 2; term++) {
                double sxi = g_p.tp[term].SXinv;
                double sx  = (double)(long long)stage[128 + 2 * term]     * g_p.tp[term].SSXinv;
                double sxx = (double)(long long)stage[128 + 2 * term + 1] * g_p.tp[term].SSXXinv;
                double mean = sx / dN;
                double Ssw = 0.0, num = 0.0;
                for (int j = 0; j < NB; j++) {
                    double sw  = (double)stage[term * NB + j] * swi;
                    double swx = (double)(long long)stage[64 + term * NB + j] * sxi;
                    double m = swx / (sw + eps);
                    double d = m - mean;
                    num += sw * d * d;
                    Ssw += sw;
                }
                double bgv = num / (Ssw + eps);
                double var = (sxx - sx * sx / dN) / (dN - 1.0);
                eta += bgv / (var + eps);
            }
            out[0] = (float)(-0.5 * eta);
        }
    }
}

extern "C" void kernel_launch(void* const* d_in, const int* in_sizes, int n_in,
                              void* d_out, int out_size) {
    const float* A = (const float*)d_in[0];
    const float* B = (const float*)d_in[1];
    int N = in_sizes[0];

    double n1 = (double)N - 1.0;
    double p01 = 0.01 * n1, p99 = 0.99 * n1;
    unsigned k01 = (unsigned)p01, k99 = (unsigned)p99;
    float f01 = (float)(p01 - (double)k01);
    float f99 = (float)(p99 - (double)k99);

    cudaFuncSetAttribute(k_fused, cudaFuncAttributeMaxDynamicSharedMemorySize, SMEM_BYTES);
    int bpsm = 0, sms = 0;
    cudaOccupancyMaxActiveBlocksPerMultiprocessor(&bpsm, k_fused, TPB, SMEM_BYTES);
    cudaDeviceGetAttribute(&sms, cudaDevAttrMultiProcessorCount, 0);
    if (bpsm < 1) bpsm = 1;
    long long grid = (long long)bpsm * (long long)sms;
    if (grid > 1024) grid = 1024;
    grid &= ~1LL;                      // even grid for the term split
    if (grid < 2) grid = 2;

    int n4 = N >> 2;
    long long halfT = (grid / 2) * TPB;
    int iters = (int)((n4 + halfT - 1) / halfT);
    int epb = iters * 4 + 8;           // per-thread elements in the split Parzen pass
    int reg = BUFSZ / (int)grid;       // per-block candidate region

    k_fused<<<(int)grid, TPB, SMEM_BYTES>>>(A, B, N, k01, k99, f01, f99, epb, reg, (float*)d_out);
}